// round 8
// baseline (speedup 1.0000x reference)
#include <cuda_runtime.h>

#define HH 512
#define WW 512
#define TPB 128           // 128 threads * 4 cols = 512 = WW
#define NBLK 1672         // 152 SMs * 11 blocks/SM == occupancy cap (ONE full wave)
#define EPS 1e-6f

// scratch for per-block partial sums + completion ticket (no cudaMalloc allowed)
__device__ float g_partials[NBLK];
__device__ unsigned int g_ticket;   // zero-init; last block resets it to 0

__device__ __forceinline__ float4 ld4(const float* __restrict__ p) {
    return *reinterpret_cast<const float4*>(p);
}

// single-MUFU approximate sqrt (max rel err ~1e-7, far below 1e-3 tolerance)
__device__ __forceinline__ float fsqrt_ap(float x) {
    float r;
    asm("sqrt.approx.f32 %0, %1;" : "=f"(r) : "f"(x));
    return r;
}

__global__ __launch_bounds__(TPB, 11)   // <=46 regs; 11 blocks/SM
void grad_loss_kernel(const float* __restrict__ in, const float* __restrict__ tg,
                      float* __restrict__ out, int total_rows, float inv_n) {
    const int t    = threadIdx.x;
    const int lane = t & 31;
    const int w    = t >> 5;              // warp 0..3; warp covers cols [w*128, w*128+128)
    const int w0   = t * 4;

    // even split of the flattened row space [0, total_rows)
    const int nb   = gridDim.x;
    const int base = total_rows / nb;
    const int rem  = total_rows % nb;
    const int bid  = blockIdx.x;
    const int rs   = bid * base + min(bid, rem);
    const int re   = rs + base + (bid < rem ? 1 : 0);

    // pi/pt point at the CURRENT row rg
    const float* pi = in + (size_t)rs * WW + w0;
    const float* pt = tg + (size_t)rs * WW + w0;

    const float4 z4 = make_float4(0.f, 0.f, 0.f, 0.f);
    float sum = 0.f;

    // double-buffered cross-warp edge exchange: [parity][array][warp]
    __shared__ float eb_l[2][2][4];   // left-most element (c.x of lane0) of each warp strip
    __shared__ float eb_r[2][2][4];   // right-most element (c.w of lane31)

    // 4 rotating slots per array: roles (u=rg-1, c=rg, n=rg+1, p=prefetch rg+2).
    // Planes are contiguous, so slots always hold TRUE row data; plane edges
    // are handled by masking at compute time.
    float4 Xi, Yi, Zi, Wi, Xt, Yt, Zt, Wt;

    Xi = (rs > 0) ? ld4(pi - WW) : z4;                    // row rs-1
    Xt = (rs > 0) ? ld4(pt - WW) : z4;
    Yi = ld4(pi);  Yt = ld4(pt);                          // row rs
    Zi = (rs + 1 < total_rows) ? ld4(pi + WW) : z4;       // row rs+1
    Zt = (rs + 1 < total_rows) ? ld4(pt + WW) : z4;

    // prologue: publish edges of row rs (parity rs&1); first step's sync orders it
    {
        const int p0 = rs & 1;
        if (lane == 0)  { eb_l[p0][0][w] = Yi.x; eb_l[p0][1][w] = Yt.x; }
        if (lane == 31) { eb_r[p0][0][w] = Yi.w; eb_r[p0][1][w] = Yt.w; }
    }

    // one pipelined step: prefetch row rg+2, exchange edges, compute row rg
    auto step = [&](float4& u_i, float4& c_i, float4& n_i, float4& p_i,
                    float4& u_t, float4& c_t, float4& n_t, float4& p_t, int rg) {
        // ---- prefetch (consumed 2 iterations from now) ----
        if (rg + 2 < total_rows) {
            p_i = ld4(pi + 2 * WW);
            p_t = ld4(pt + 2 * WW);
        } else {
            p_i = z4; p_t = z4;
        }

        const int p0 = rg & 1;

        __syncthreads();   // orders: prev-step edge writes < this-step reads,
                           // this-step reads/writes split across parities

        // interior horizontal neighbors via warp shuffle
        float lci = __shfl_up_sync(0xffffffffu, c_i.w, 1);
        float lct = __shfl_up_sync(0xffffffffu, c_t.w, 1);
        float rci = __shfl_down_sync(0xffffffffu, c_i.x, 1);
        float rct = __shfl_down_sync(0xffffffffu, c_t.x, 1);
        // cross-warp edges from smem (image edges -> 0, SAME-pad semantics)
        if (lane == 0) {
            lci = (w > 0) ? eb_r[p0][0][w - 1] : 0.f;
            lct = (w > 0) ? eb_r[p0][1][w - 1] : 0.f;
        }
        if (lane == 31) {
            rci = (w < 3) ? eb_l[p0][0][w + 1] : 0.f;
            rct = (w < 3) ? eb_l[p0][1][w + 1] : 0.f;
        }

        // publish NEXT row's (rg+1) edges into the other parity buffer
        if (lane == 0)  { eb_l[p0 ^ 1][0][w] = n_i.x; eb_l[p0 ^ 1][1][w] = n_t.x; }
        if (lane == 31) { eb_r[p0 ^ 1][0][w] = n_i.w; eb_r[p0 ^ 1][1][w] = n_t.w; }

        const int r = rg & (HH - 1);
        // plane-edge masks: u slot is dead after this step -> overwrite;
        // n slot must survive (becomes c) -> masked temps
        if (r == 0) { u_i = z4; u_t = z4; }
        const float4 nn_i = (r == HH - 1) ? z4 : n_i;
        const float4 nn_t = (r == HH - 1) ? z4 : n_t;

        float gv, gh, a, b;

        gv = nn_i.x - u_i.x; gh = c_i.y - lci;
        a  = fsqrt_ap(fmaf(gv, gv, fmaf(gh, gh, EPS)));
        gv = nn_t.x - u_t.x; gh = c_t.y - lct;
        b  = fsqrt_ap(fmaf(gv, gv, fmaf(gh, gh, EPS)));
        sum += fabsf(a - b);

        gv = nn_i.y - u_i.y; gh = c_i.z - c_i.x;
        a  = fsqrt_ap(fmaf(gv, gv, fmaf(gh, gh, EPS)));
        gv = nn_t.y - u_t.y; gh = c_t.z - c_t.x;
        b  = fsqrt_ap(fmaf(gv, gv, fmaf(gh, gh, EPS)));
        sum += fabsf(a - b);

        gv = nn_i.z - u_i.z; gh = c_i.w - c_i.y;
        a  = fsqrt_ap(fmaf(gv, gv, fmaf(gh, gh, EPS)));
        gv = nn_t.z - u_t.z; gh = c_t.w - c_t.y;
        b  = fsqrt_ap(fmaf(gv, gv, fmaf(gh, gh, EPS)));
        sum += fabsf(a - b);

        gv = nn_i.w - u_i.w; gh = rci - c_i.z;
        a  = fsqrt_ap(fmaf(gv, gv, fmaf(gh, gh, EPS)));
        gv = nn_t.w - u_t.w; gh = rct - c_t.z;
        b  = fsqrt_ap(fmaf(gv, gv, fmaf(gh, gh, EPS)));
        sum += fabsf(a - b);

        pi += WW; pt += WW;
    };

    int rg = rs;
    for (; rg + 4 <= re; rg += 4) {
        step(Xi, Yi, Zi, Wi, Xt, Yt, Zt, Wt, rg);
        step(Yi, Zi, Wi, Xi, Yt, Zt, Wt, Xt, rg + 1);
        step(Zi, Wi, Xi, Yi, Zt, Wt, Xt, Yt, rg + 2);
        step(Wi, Xi, Yi, Zi, Wt, Xt, Yt, Zt, rg + 3);
    }
    if (rg < re) { step(Xi, Yi, Zi, Wi, Xt, Yt, Zt, Wt, rg); ++rg; }
    if (rg < re) { step(Yi, Zi, Wi, Xi, Yt, Zt, Wt, Xt, rg); ++rg; }
    if (rg < re) { step(Zi, Wi, Xi, Yi, Zt, Wt, Xt, Yt, rg); ++rg; }

    // block reduction: warp shfl, then across 4 warps via smem
    #pragma unroll
    for (int o = 16; o > 0; o >>= 1)
        sum += __shfl_down_sync(0xffffffffu, sum, o);

    __shared__ float ws[TPB / 32];
    __shared__ bool is_last;
    if ((t & 31) == 0) ws[t >> 5] = sum;
    __syncthreads();

    if (t == 0) {
        float s = ws[0] + ws[1] + ws[2] + ws[3];
        g_partials[bid] = s;
        __threadfence();                               // partial visible before ticket
        unsigned done = atomicAdd(&g_ticket, 1u);
        is_last = (done == (unsigned)(nb - 1));
    }
    __syncthreads();

    if (is_last) {
        const volatile float* vp = (const volatile float*)g_partials;
        float s = 0.f;
        for (int i = t; i < nb; i += TPB)
            s += vp[i];

        #pragma unroll
        for (int o = 16; o > 0; o >>= 1)
            s += __shfl_down_sync(0xffffffffu, s, o);

        if ((t & 31) == 0) ws[t >> 5] = s;
        __syncthreads();
        if (t == 0) {
            out[0] = (ws[0] + ws[1] + ws[2] + ws[3]) * inv_n;
            g_ticket = 0;                              // reset for next graph replay
        }
    }
}

extern "C" void kernel_launch(void* const* d_in, const int* in_sizes, int n_in,
                              void* d_out, int out_size) {
    const float* in = (const float*)d_in[0];
    const float* tg = (const float*)d_in[1];
    float* out = (float*)d_out;

    const int total = in_sizes[0];                 // 32*3*512*512
    const int total_rows = total / WW;             // 49152

    grad_loss_kernel<<<NBLK, TPB>>>(in, tg, out, total_rows, 1.0f / (float)total);
}

// round 9
// speedup vs baseline: 2.0265x; 2.0265x over previous
#include <cuda_runtime.h>

#define HH 512
#define WW 512
#define TPB 128           // 128 threads * 4 cols = 512 = WW
#define NBLK 1672         // 152 SMs * 11 blocks/SM == occupancy cap (ONE full wave)
#define EPS 1e-6f

// scratch for per-block partial sums + completion ticket (no cudaMalloc allowed)
__device__ float g_partials[NBLK];
__device__ unsigned int g_ticket;   // zero-init; last block resets it to 0

__device__ __forceinline__ float4 ld4(const float* __restrict__ p) {
    return *reinterpret_cast<const float4*>(p);
}

// single-MUFU approximate sqrt (max rel err ~1e-7, far below 1e-3 tolerance)
__device__ __forceinline__ float fsqrt_ap(float x) {
    float r;
    asm("sqrt.approx.f32 %0, %1;" : "=f"(r) : "f"(x));
    return r;
}

__global__ __launch_bounds__(TPB, 11)   // <=46 regs; 11 blocks/SM
void grad_loss_kernel(const float* __restrict__ in, const float* __restrict__ tg,
                      float* __restrict__ out, int total_rows, float inv_n) {
    const int t    = threadIdx.x;
    const int lane = t & 31;
    const int w0   = t * 4;
    const bool eL  = (lane == 0)  && (w0 > 0);        // this lane loads a left edge
    const bool eR  = (lane == 31) && (w0 + 4 < WW);   // this lane loads a right edge

    // even split of the flattened row space [0, total_rows)
    const int nb   = gridDim.x;
    const int base = total_rows / nb;
    const int rem  = total_rows % nb;
    const int bid  = blockIdx.x;
    const int rs   = bid * base + min(bid, rem);
    const int re   = rs + base + (bid < rem ? 1 : 0);

    // pi/pt point at the CURRENT row rg
    const float* pi = in + (size_t)rs * WW + w0;
    const float* pt = tg + (size_t)rs * WW + w0;

    const float4 z4 = make_float4(0.f, 0.f, 0.f, 0.f);
    float sum = 0.f;

    // 3 rotating row slots per array (u=rg-1, c=rg, n=rg+1); plane edges by masking
    float4 Xi, Yi, Zi, Xt, Yt, Zt;
    // current row's warp-edge scalars (valid for the row c holds)
    float lei, let_, rei, ret_;

    Xi = (rs > 0) ? ld4(pi - WW) : z4;   Xt = (rs > 0) ? ld4(pt - WW) : z4;
    Yi = ld4(pi);                        Yt = ld4(pt);
    lei  = eL ? pi[-1] : 0.f;            let_ = eL ? pt[-1] : 0.f;
    rei  = eR ? pi[4]  : 0.f;            ret_ = eR ? pt[4]  : 0.f;

    // one step: load row rg+1 (vector) + PREFETCH row rg+1's edge scalars,
    // compute row rg from (u, c, n-masked, current edges), rotate at call site
    auto step = [&](float4& u_i, float4& c_i, float4& n_i,
                    float4& u_t, float4& c_t, float4& n_t, int rg) {
        const bool hasN = (rg + 1 < total_rows);
        if (hasN) {
            n_i = ld4(pi + WW); n_t = ld4(pt + WW);
        } else {
            n_i = z4; n_t = z4;
        }
        // edge prefetch for NEXT iteration (row rg+1) — consumed one full
        // iteration later (~550 cyc of cover), predicated to edge lanes only
        const float nlei  = (eL && hasN) ? pi[WW - 1] : 0.f;
        const float nlet  = (eL && hasN) ? pt[WW - 1] : 0.f;
        const float nrei  = (eR && hasN) ? pi[WW + 4] : 0.f;
        const float nret  = (eR && hasN) ? pt[WW + 4] : 0.f;

        const int r = rg & (HH - 1);
        if (r == 0) { u_i = z4; u_t = z4; }              // plane-start mask (slot dead after)
        const float4 nn_i = (r == HH - 1) ? z4 : n_i;    // plane-end mask (slot survives)
        const float4 nn_t = (r == HH - 1) ? z4 : n_t;

        // horizontal neighbors: shuffles for interior, prefetched regs for edges
        float lci = __shfl_up_sync(0xffffffffu, c_i.w, 1);
        float lct = __shfl_up_sync(0xffffffffu, c_t.w, 1);
        float rci = __shfl_down_sync(0xffffffffu, c_i.x, 1);
        float rct = __shfl_down_sync(0xffffffffu, c_t.x, 1);
        if (lane == 0)  { lci = lei; lct = let_; }
        if (lane == 31) { rci = rei; rct = ret_; }

        float gv, gh, a, b;

        gv = nn_i.x - u_i.x; gh = c_i.y - lci;
        a  = fsqrt_ap(fmaf(gv, gv, fmaf(gh, gh, EPS)));
        gv = nn_t.x - u_t.x; gh = c_t.y - lct;
        b  = fsqrt_ap(fmaf(gv, gv, fmaf(gh, gh, EPS)));
        sum += fabsf(a - b);

        gv = nn_i.y - u_i.y; gh = c_i.z - c_i.x;
        a  = fsqrt_ap(fmaf(gv, gv, fmaf(gh, gh, EPS)));
        gv = nn_t.y - u_t.y; gh = c_t.z - c_t.x;
        b  = fsqrt_ap(fmaf(gv, gv, fmaf(gh, gh, EPS)));
        sum += fabsf(a - b);

        gv = nn_i.z - u_i.z; gh = c_i.w - c_i.y;
        a  = fsqrt_ap(fmaf(gv, gv, fmaf(gh, gh, EPS)));
        gv = nn_t.z - u_t.z; gh = c_t.w - c_t.y;
        b  = fsqrt_ap(fmaf(gv, gv, fmaf(gh, gh, EPS)));
        sum += fabsf(a - b);

        gv = nn_i.w - u_i.w; gh = rci - c_i.z;
        a  = fsqrt_ap(fmaf(gv, gv, fmaf(gh, gh, EPS)));
        gv = nn_t.w - u_t.w; gh = rct - c_t.z;
        b  = fsqrt_ap(fmaf(gv, gv, fmaf(gh, gh, EPS)));
        sum += fabsf(a - b);

        // rotate edge regs (row slots rotate via call-site permutation)
        lei = nlei; let_ = nlet; rei = nrei; ret_ = nret;
        pi += WW; pt += WW;
    };

    int rg = rs;
    for (; rg + 3 <= re; rg += 3) {
        step(Xi, Yi, Zi, Xt, Yt, Zt, rg);
        step(Yi, Zi, Xi, Yt, Zt, Xt, rg + 1);
        step(Zi, Xi, Yi, Zt, Xt, Yt, rg + 2);
    }
    if (rg < re) { step(Xi, Yi, Zi, Xt, Yt, Zt, rg); ++rg; }
    if (rg < re) { step(Yi, Zi, Xi, Yt, Zt, Xt, rg); ++rg; }

    // block reduction: warp shfl, then across 4 warps via smem
    #pragma unroll
    for (int o = 16; o > 0; o >>= 1)
        sum += __shfl_down_sync(0xffffffffu, sum, o);

    __shared__ float ws[TPB / 32];
    __shared__ bool is_last;
    if ((t & 31) == 0) ws[t >> 5] = sum;
    __syncthreads();

    if (t == 0) {
        float s = ws[0] + ws[1] + ws[2] + ws[3];
        g_partials[bid] = s;
        __threadfence();                               // partial visible before ticket
        unsigned done = atomicAdd(&g_ticket, 1u);
        is_last = (done == (unsigned)(nb - 1));
    }
    __syncthreads();

    if (is_last) {
        const volatile float* vp = (const volatile float*)g_partials;
        float s = 0.f;
        for (int i = t; i < nb; i += TPB)
            s += vp[i];

        #pragma unroll
        for (int o = 16; o > 0; o >>= 1)
            s += __shfl_down_sync(0xffffffffu, s, o);

        if ((t & 31) == 0) ws[t >> 5] = s;
        __syncthreads();
        if (t == 0) {
            out[0] = (ws[0] + ws[1] + ws[2] + ws[3]) * inv_n;
            g_ticket = 0;                              // reset for next graph replay
        }
    }
}

extern "C" void kernel_launch(void* const* d_in, const int* in_sizes, int n_in,
                              void* d_out, int out_size) {
    const float* in = (const float*)d_in[0];
    const float* tg = (const float*)d_in[1];
    float* out = (float*)d_out;

    const int total = in_sizes[0];                 // 32*3*512*512
    const int total_rows = total / WW;             // 49152

    grad_loss_kernel<<<NBLK, TPB>>>(in, tg, out, total_rows, 1.0f / (float)total);
}

// round 10
// speedup vs baseline: 2.1413x; 1.0566x over previous
#include <cuda_runtime.h>

#define HH 512
#define WW 512
#define TPB 128           // 128 threads * 4 cols = 512 = WW
#define NMAIN 1728        // maskless streaming blocks
#define NCORR 95          // internal plane-boundary correction blocks
#define NBLK (NMAIN + NCORR)   // 1823 ~= 152 SMs * 12 blocks/SM (one wave)
#define EPS 1e-6f

// scratch for per-block partial sums + completion ticket (no cudaMalloc allowed)
__device__ float g_partials[NBLK];
__device__ unsigned int g_ticket;   // zero-init; last block resets it to 0

__device__ __forceinline__ float4 ld4(const float* __restrict__ p) {
    return *reinterpret_cast<const float4*>(p);
}

// single-MUFU approximate sqrt (max rel err ~1e-7, far below 1e-3 tolerance)
__device__ __forceinline__ float fsqrt_ap(float x) {
    float r;
    asm("sqrt.approx.f32 %0, %1;" : "=f"(r) : "f"(x));
    return r;
}

__global__ __launch_bounds__(TPB, 12)   // <=40 regs; 12 blocks/SM
void grad_loss_kernel(const float* __restrict__ in, const float* __restrict__ tg,
                      float* __restrict__ out, int total_rows, float inv_n) {
    const int t    = threadIdx.x;
    const int lane = t & 31;
    const int w0   = t * 4;
    const bool hasL = (w0 > 0);
    const bool hasR = (w0 + 4 < WW);
    const int bid  = blockIdx.x;

    const float4 z4 = make_float4(0.f, 0.f, 0.f, 0.f);
    float sum = 0.f;

    if (bid < NMAIN) {
        // ================= MAIN: maskless flattened stencil =================
        const int base = total_rows / NMAIN;
        const int rem  = total_rows % NMAIN;
        const int rs   = bid * base + min(bid, rem);
        const int re   = rs + base + (bid < rem ? 1 : 0);
        // last block peels its final row (its n-row would be OOB)
        const int re_loop = (re == total_rows) ? re - 1 : re;

        const float* pi = in + (size_t)rs * WW + w0;
        const float* pt = tg + (size_t)rs * WW + w0;

        // compute one row from (u, c, n); bumps pointers
        auto rowmath = [&](const float4& u_i, const float4& c_i, const float4& n_i,
                           const float4& u_t, const float4& c_t, const float4& n_t) {
            float lci = __shfl_up_sync(0xffffffffu, c_i.w, 1);
            float lct = __shfl_up_sync(0xffffffffu, c_t.w, 1);
            float rci = __shfl_down_sync(0xffffffffu, c_i.x, 1);
            float rct = __shfl_down_sync(0xffffffffu, c_t.x, 1);
            if (lane == 0)  { lci = hasL ? pi[-1] : 0.f; lct = hasL ? pt[-1] : 0.f; }
            if (lane == 31) { rci = hasR ? pi[4]  : 0.f; rct = hasR ? pt[4]  : 0.f; }

            float gv, gh, a, b;

            gv = n_i.x - u_i.x; gh = c_i.y - lci;
            a  = fsqrt_ap(fmaf(gv, gv, fmaf(gh, gh, EPS)));
            gv = n_t.x - u_t.x; gh = c_t.y - lct;
            b  = fsqrt_ap(fmaf(gv, gv, fmaf(gh, gh, EPS)));
            sum += fabsf(a - b);

            gv = n_i.y - u_i.y; gh = c_i.z - c_i.x;
            a  = fsqrt_ap(fmaf(gv, gv, fmaf(gh, gh, EPS)));
            gv = n_t.y - u_t.y; gh = c_t.z - c_t.x;
            b  = fsqrt_ap(fmaf(gv, gv, fmaf(gh, gh, EPS)));
            sum += fabsf(a - b);

            gv = n_i.z - u_i.z; gh = c_i.w - c_i.y;
            a  = fsqrt_ap(fmaf(gv, gv, fmaf(gh, gh, EPS)));
            gv = n_t.z - u_t.z; gh = c_t.w - c_t.y;
            b  = fsqrt_ap(fmaf(gv, gv, fmaf(gh, gh, EPS)));
            sum += fabsf(a - b);

            gv = n_i.w - u_i.w; gh = rci - c_i.z;
            a  = fsqrt_ap(fmaf(gv, gv, fmaf(gh, gh, EPS)));
            gv = n_t.w - u_t.w; gh = rct - c_t.z;
            b  = fsqrt_ap(fmaf(gv, gv, fmaf(gh, gh, EPS)));
            sum += fabsf(a - b);

            pi += WW; pt += WW;
        };

        // 3 rotating row slots; NO plane-edge masks (fixed by correction blocks)
        float4 Xi, Yi, Zi, Xt, Yt, Zt;
        Xi = (rs > 0) ? ld4(pi - WW) : z4;   Xt = (rs > 0) ? ld4(pt - WW) : z4;
        Yi = ld4(pi);                        Yt = ld4(pt);

        auto step = [&](float4& u_i, float4& c_i, float4& n_i,
                        float4& u_t, float4& c_t, float4& n_t) {
            n_i = ld4(pi + WW);              // always valid: row+1 < total_rows
            n_t = ld4(pt + WW);
            rowmath(u_i, c_i, n_i, u_t, c_t, n_t);
        };

        const int m = re_loop - rs;
        int k = 0;
        for (; k + 3 <= m; k += 3) {
            step(Xi, Yi, Zi, Xt, Yt, Zt);
            step(Yi, Zi, Xi, Yt, Zt, Xt);
            step(Zi, Xi, Yi, Zt, Xt, Yt);
        }
        if (k < m) { step(Xi, Yi, Zi, Xt, Yt, Zt); ++k; }
        if (k < m) { step(Yi, Zi, Xi, Yt, Zt, Xt); ++k; }

        // last block: final row of tensor with n = 0 (reload u,c — one-time L2 hit)
        if (re == total_rows) {
            float4 cu_i = ld4(pi - WW), cc_i = ld4(pi);
            float4 cu_t = ld4(pt - WW), cc_t = ld4(pt);
            rowmath(cu_i, cc_i, z4, cu_t, cc_t, z4);
        }
    } else {
        // ======= CORRECTION: fix the 95 internal plane boundaries =======
        // boundary p separates plane p-1 (last row 512p-1) from plane p (row 512p).
        // Main pass used flattened neighbors there; add (right - wrong).
        const int p    = bid - NMAIN + 1;          // 1..95
        const int rowa = p * HH;                   // plane-start row
        #pragma unroll
        for (int rr = 0; rr < 2; ++rr) {
            const int row = rr ? rowa : (rowa - 1);
            const bool isStart = (rr == 1);        // r==0: right gv = dn; r==511: right gv = -up
            const float* ri = in + (size_t)row * WW;
            const float* rt = tg + (size_t)row * WW;
            #pragma unroll
            for (int j4 = 0; j4 < 4; ++j4) {
                const int j = w0 + j4;
                const float l_i = (j > 0)      ? ri[j - 1] : 0.f;
                const float r_i = (j < WW - 1) ? ri[j + 1] : 0.f;
                const float l_t = (j > 0)      ? rt[j - 1] : 0.f;
                const float r_t = (j < WW - 1) ? rt[j + 1] : 0.f;
                const float gh_i = r_i - l_i, gh_t = r_t - l_t;
                const float up_i = ri[j - WW], dn_i = ri[j + WW];
                const float up_t = rt[j - WW], dn_t = rt[j + WW];
                const float gvw_i = dn_i - up_i, gvw_t = dn_t - up_t;         // wrong (flattened)
                const float gvr_i = isStart ? dn_i : -up_i;                    // right (zero-pad)
                const float gvr_t = isStart ? dn_t : -up_t;
                const float aw = fsqrt_ap(fmaf(gvw_i, gvw_i, fmaf(gh_i, gh_i, EPS)));
                const float bw = fsqrt_ap(fmaf(gvw_t, gvw_t, fmaf(gh_t, gh_t, EPS)));
                const float ar = fsqrt_ap(fmaf(gvr_i, gvr_i, fmaf(gh_i, gh_i, EPS)));
                const float br = fsqrt_ap(fmaf(gvr_t, gvr_t, fmaf(gh_t, gh_t, EPS)));
                sum += fabsf(ar - br) - fabsf(aw - bw);
            }
        }
    }

    // ---------- common: block reduction + last-block-ticket finisher ----------
    #pragma unroll
    for (int o = 16; o > 0; o >>= 1)
        sum += __shfl_down_sync(0xffffffffu, sum, o);

    __shared__ float ws[TPB / 32];
    __shared__ bool is_last;
    if ((t & 31) == 0) ws[t >> 5] = sum;
    __syncthreads();

    if (t == 0) {
        float s = ws[0] + ws[1] + ws[2] + ws[3];
        g_partials[bid] = s;
        __threadfence();                               // partial visible before ticket
        unsigned done = atomicAdd(&g_ticket, 1u);
        is_last = (done == (unsigned)(NBLK - 1));
    }
    __syncthreads();

    if (is_last) {
        const volatile float* vp = (const volatile float*)g_partials;
        float s = 0.f;
        for (int i = t; i < NBLK; i += TPB)
            s += vp[i];

        #pragma unroll
        for (int o = 16; o > 0; o >>= 1)
            s += __shfl_down_sync(0xffffffffu, s, o);

        if ((t & 31) == 0) ws[t >> 5] = s;
        __syncthreads();
        if (t == 0) {
            out[0] = (ws[0] + ws[1] + ws[2] + ws[3]) * inv_n;
            g_ticket = 0;                              // reset for next graph replay
        }
    }
}

extern "C" void kernel_launch(void* const* d_in, const int* in_sizes, int n_in,
                              void* d_out, int out_size) {
    const float* in = (const float*)d_in[0];
    const float* tg = (const float*)d_in[1];
    float* out = (float*)d_out;

    const int total = in_sizes[0];                 // 32*3*512*512
    const int total_rows = total / WW;             // 49152

    grad_loss_kernel<<<NBLK, TPB>>>(in, tg, out, total_rows, 1.0f / (float)total);
}

// round 11
// speedup vs baseline: 2.5222x; 1.1779x over previous
#include <cuda_runtime.h>

#define HH 512
#define WW 512
#define TPB 128           // 4 warps per block; each WARP owns full 512-col rows
#define NBLK 608          // 152 SMs * 4 blocks/SM (one wave at the reg-limited cap)
#define EPS 1e-6f

// scratch for per-block partial sums + completion ticket (no cudaMalloc allowed)
__device__ float g_partials[NBLK];
__device__ unsigned int g_ticket;   // zero-init; last block resets it to 0

__device__ __forceinline__ float4 ld4(const float* __restrict__ p) {
    return *reinterpret_cast<const float4*>(p);
}

// single-MUFU approximate sqrt (max rel err ~1e-7, far below 1e-3 tolerance)
__device__ __forceinline__ float fsqrt_ap(float x) {
    float r;
    asm("sqrt.approx.f32 %0, %1;" : "=f"(r) : "f"(x));
    return r;
}

__global__ __launch_bounds__(TPB, 4)   // up to 128 regs; 4 blocks/SM
void grad_loss_kernel(const float* __restrict__ in, const float* __restrict__ tg,
                      float* __restrict__ out, int total_rows, float inv_n) {
    const int t     = threadIdx.x;
    const int lane  = t & 31;
    const int wid   = t >> 5;
    const int gw    = blockIdx.x * 4 + wid;       // global warp id
    const int laneL = (lane + 31) & 31;           // rotate: lane reads lane-1 (wrap)
    const int laneR = (lane + 1) & 31;            // rotate: lane reads lane+1 (wrap)

    // contiguous row slice per warp over the flattened row space
    const int nw   = NBLK * 4;
    const int base = total_rows / nw;
    const int rem  = total_rows % nw;
    const int ws   = gw * base + min(gw, rem);
    const int we   = ws + base + (gw < rem ? 1 : 0);

    // lane covers cols {k*128 + lane*4 .. +4}, k=0..3 (chunk loads are 512B coalesced)
    const float* pi = in + (size_t)ws * WW + lane * 4;
    const float* pt = tg + (size_t)ws * WW + lane * 4;

    const float4 z4 = make_float4(0.f, 0.f, 0.f, 0.f);
    float sum = 0.f;

    // 3 rotating row buffers per array, 4 chunks each: roles (u, c, n)
    float4 Xi[4], Yi[4], Zi[4], Xt[4], Yt[4], Zt[4];

    #pragma unroll
    for (int k = 0; k < 4; ++k) {
        Xi[k] = (ws > 0) ? ld4(pi - WW + k * 128) : z4;   // row ws-1
        Xt[k] = (ws > 0) ? ld4(pt - WW + k * 128) : z4;
        Yi[k] = ld4(pi + k * 128);                        // row ws
        Yt[k] = ld4(pt + k * 128);
    }

    // one step: compute row rg from (u, c, n); r is WARP-UNIFORM -> cheap branches
    auto step = [&](float4 (&u_i)[4], float4 (&c_i)[4], float4 (&n_i)[4],
                    float4 (&u_t)[4], float4 (&c_t)[4], float4 (&n_t)[4], int rg) {
        const int r = rg & (HH - 1);
        if (r != HH - 1) {                    // common path: load next row
            #pragma unroll
            for (int k = 0; k < 4; ++k) {
                n_i[k] = ld4(pi + WW + k * 128);
                n_t[k] = ld4(pt + WW + k * 128);
            }
        } else {                              // plane-last row: zero-pad below
            #pragma unroll
            for (int k = 0; k < 4; ++k) { n_i[k] = z4; n_t[k] = z4; }
        }
        if (r == 0) {                         // plane-first row: zero-pad above
            #pragma unroll
            for (int k = 0; k < 4; ++k) { u_i[k] = z4; u_t[k] = z4; }
        }

        #pragma unroll
        for (int k = 0; k < 4; ++k) {
            // horizontal neighbors: rotate-shuffles, register-sourced, no loads.
            // lane31 feeds lane0 the previous chunk's .w (or image edge 0);
            // lane0 feeds lane31 the next chunk's .x (or image edge 0).
            float xl_i = (lane == 31) ? (k > 0 ? c_i[k - 1].w : 0.f) : c_i[k].w;
            float xl_t = (lane == 31) ? (k > 0 ? c_t[k - 1].w : 0.f) : c_t[k].w;
            const float lci = __shfl_sync(0xffffffffu, xl_i, laneL);
            const float lct = __shfl_sync(0xffffffffu, xl_t, laneL);
            float xr_i = (lane == 0) ? (k < 3 ? c_i[k + 1].x : 0.f) : c_i[k].x;
            float xr_t = (lane == 0) ? (k < 3 ? c_t[k + 1].x : 0.f) : c_t[k].x;
            const float rci = __shfl_sync(0xffffffffu, xr_i, laneR);
            const float rct = __shfl_sync(0xffffffffu, xr_t, laneR);

            float gv, gh, a, b;

            gv = n_i[k].x - u_i[k].x; gh = c_i[k].y - lci;
            a  = fsqrt_ap(fmaf(gv, gv, fmaf(gh, gh, EPS)));
            gv = n_t[k].x - u_t[k].x; gh = c_t[k].y - lct;
            b  = fsqrt_ap(fmaf(gv, gv, fmaf(gh, gh, EPS)));
            sum += fabsf(a - b);

            gv = n_i[k].y - u_i[k].y; gh = c_i[k].z - c_i[k].x;
            a  = fsqrt_ap(fmaf(gv, gv, fmaf(gh, gh, EPS)));
            gv = n_t[k].y - u_t[k].y; gh = c_t[k].z - c_t[k].x;
            b  = fsqrt_ap(fmaf(gv, gv, fmaf(gh, gh, EPS)));
            sum += fabsf(a - b);

            gv = n_i[k].z - u_i[k].z; gh = c_i[k].w - c_i[k].y;
            a  = fsqrt_ap(fmaf(gv, gv, fmaf(gh, gh, EPS)));
            gv = n_t[k].z - u_t[k].z; gh = c_t[k].w - c_t[k].y;
            b  = fsqrt_ap(fmaf(gv, gv, fmaf(gh, gh, EPS)));
            sum += fabsf(a - b);

            gv = n_i[k].w - u_i[k].w; gh = rci - c_i[k].z;
            a  = fsqrt_ap(fmaf(gv, gv, fmaf(gh, gh, EPS)));
            gv = n_t[k].w - u_t[k].w; gh = rct - c_t[k].z;
            b  = fsqrt_ap(fmaf(gv, gv, fmaf(gh, gh, EPS)));
            sum += fabsf(a - b);
        }

        // plane-last row zeroed n, but next iteration needs c = real row rg+1:
        // rare uniform reload (once per 512 rows; L2 hit)
        if (r == HH - 1 && rg + 1 < total_rows) {
            #pragma unroll
            for (int k = 0; k < 4; ++k) {
                n_i[k] = ld4(pi + WW + k * 128);
                n_t[k] = ld4(pt + WW + k * 128);
            }
        }

        pi += WW; pt += WW;
    };

    int rg = ws;
    for (; rg + 3 <= we; rg += 3) {
        step(Xi, Yi, Zi, Xt, Yt, Zt, rg);
        step(Yi, Zi, Xi, Yt, Zt, Xt, rg + 1);
        step(Zi, Xi, Yi, Zt, Xt, Yt, rg + 2);
    }
    if (rg < we) { step(Xi, Yi, Zi, Xt, Yt, Zt, rg); ++rg; }
    if (rg < we) { step(Yi, Zi, Xi, Yt, Zt, Xt, rg); ++rg; }

    // ---------- block reduction + last-block-ticket finisher ----------
    #pragma unroll
    for (int o = 16; o > 0; o >>= 1)
        sum += __shfl_down_sync(0xffffffffu, sum, o);

    __shared__ float wsum[TPB / 32];
    __shared__ bool is_last;
    if (lane == 0) wsum[wid] = sum;
    __syncthreads();

    if (t == 0) {
        float s = wsum[0] + wsum[1] + wsum[2] + wsum[3];
        g_partials[blockIdx.x] = s;
        __threadfence();                               // partial visible before ticket
        unsigned done = atomicAdd(&g_ticket, 1u);
        is_last = (done == (unsigned)(NBLK - 1));
    }
    __syncthreads();

    if (is_last) {
        const volatile float* vp = (const volatile float*)g_partials;
        float s = 0.f;
        for (int i = t; i < NBLK; i += TPB)
            s += vp[i];

        #pragma unroll
        for (int o = 16; o > 0; o >>= 1)
            s += __shfl_down_sync(0xffffffffu, s, o);

        if (lane == 0) wsum[wid] = s;
        __syncthreads();
        if (t == 0) {
            out[0] = (wsum[0] + wsum[1] + wsum[2] + wsum[3]) * inv_n;
            g_ticket = 0;                              // reset for next graph replay
        }
    }
}

extern "C" void kernel_launch(void* const* d_in, const int* in_sizes, int n_in,
                              void* d_out, int out_size) {
    const float* in = (const float*)d_in[0];
    const float* tg = (const float*)d_in[1];
    float* out = (float*)d_out;

    const int total = in_sizes[0];                 // 32*3*512*512
    const int total_rows = total / WW;             // 49152

    grad_loss_kernel<<<NBLK, TPB>>>(in, tg, out, total_rows, 1.0f / (float)total);
}